// round 1
// baseline (speedup 1.0000x reference)
#include <cuda_runtime.h>
#include <cstdint>

#define NB   2048
#define INS  512
#define SEQL 128
#define NH   12
#define NOUT 3
#define BPB  4   // batches per block in pre_kernel

// scratch (allocation-free contract: __device__ globals)
__device__ float g_pre[(size_t)SEQL * NB * NH];   // [s][b][h]  ~12.6 MB
__device__ float g_hbwd[NB * NH];

__device__ __forceinline__ unsigned long long fma2(unsigned long long a,
                                                   unsigned long long b,
                                                   unsigned long long c) {
    unsigned long long d;
    asm("fma.rn.f32x2 %0, %1, %2, %3;" : "=l"(d) : "l"(a), "l"(b), "l"(c));
    return d;
}
__device__ __forceinline__ float lo32f(unsigned long long u) {
    return __uint_as_float((unsigned)u);
}
__device__ __forceinline__ float hi32f(unsigned long long u) {
    return __uint_as_float((unsigned)(u >> 32));
}

// ---------------------------------------------------------------------------
// Kernel 1: pre[s,b,h] = sum_i emb[x[b,i], s] * w_ih_f[h,i]
// block = 128 threads = 4 warps = 4 batches; lane owns s in [4*lane, 4*lane+4)
// w_ih_f duplicated as (w,w) f32x2 pairs in smem; emb row read as one
// coalesced LDG.128 per warp per i; 24 fma.rn.f32x2 per i per thread.
// ---------------------------------------------------------------------------
extern "C" __global__ void __launch_bounds__(128)
pre_kernel(const int* __restrict__ x, const float* __restrict__ emb,
           const float* __restrict__ wih) {
    extern __shared__ char dynsmem[];
    ulonglong2* w2 = (ulonglong2*)dynsmem;                      // [INS*6] = 48 KB
    int* xs = (int*)(dynsmem + (size_t)INS * 6 * sizeof(ulonglong2)); // [BPB*INS]

    const int tid = threadIdx.x;
    const int b0 = blockIdx.x * BPB;

    // stage duplicated weights: float2 slot (i*NH + h) = {w[h,i], w[h,i]}
    for (int t = tid; t < INS * NH; t += 128) {
        int i = t / NH, h = t % NH;
        float w = wih[h * INS + i];
        ((float2*)w2)[(size_t)i * NH + h] = make_float2(w, w);
    }
    for (int t = tid; t < BPB * INS; t += 128)
        xs[t] = x[(size_t)b0 * INS + t];
    __syncthreads();

    const int wb = tid >> 5;
    const int lane = tid & 31;
    const int b = b0 + wb;
    const int* xrow = xs + wb * INS;

    unsigned long long acc[NH][2];
#pragma unroll
    for (int h = 0; h < NH; h++) { acc[h][0] = 0ull; acc[h][1] = 0ull; }

#pragma unroll 4
    for (int i = 0; i < INS; i++) {
        int idx = xrow[i];
        // e = emb[idx, 4*lane .. 4*lane+3]  (whole warp covers one 512B row)
        ulonglong2 e = *((const ulonglong2*)(emb + (size_t)idx * SEQL) + lane);
        const ulonglong2* wv = w2 + (size_t)i * 6;
#pragma unroll
        for (int k = 0; k < 6; k++) {
            ulonglong2 wp = wv[k];  // pairs for h=2k, 2k+1 (broadcast LDS.128)
            acc[2 * k    ][0] = fma2(e.x, wp.x, acc[2 * k    ][0]);
            acc[2 * k    ][1] = fma2(e.y, wp.x, acc[2 * k    ][1]);
            acc[2 * k + 1][0] = fma2(e.x, wp.y, acc[2 * k + 1][0]);
            acc[2 * k + 1][1] = fma2(e.y, wp.y, acc[2 * k + 1][1]);
        }
    }

    const int s0 = lane * 4;
#pragma unroll
    for (int sp = 0; sp < 2; sp++) {
#pragma unroll
        for (int hf = 0; hf < 2; hf++) {
            int s = s0 + 2 * sp + hf;
            float v[NH];
#pragma unroll
            for (int h = 0; h < NH; h++)
                v[h] = hf ? hi32f(acc[h][sp]) : lo32f(acc[h][sp]);
            float4* d = (float4*)(g_pre + (size_t)s * NB * NH + (size_t)b * NH);
            d[0] = make_float4(v[0], v[1], v[2], v[3]);
            d[1] = make_float4(v[4], v[5], v[6], v[7]);
            d[2] = make_float4(v[8], v[9], v[10], v[11]);
        }
    }
}

// ---------------------------------------------------------------------------
// Kernel 2: h_bwd[b,h] = tanh( sum_i emb[x[b,i],127]*w_ih_r[h,i] + b_ih_r + b_hh_r )
// ---------------------------------------------------------------------------
extern "C" __global__ void __launch_bounds__(128)
bwd_kernel(const int* __restrict__ x, const float* __restrict__ emb,
           const float* __restrict__ wir, const float* __restrict__ bir,
           const float* __restrict__ bhr) {
    const int b = blockIdx.x, tid = threadIdx.x;
    float p[NH];
#pragma unroll
    for (int h = 0; h < NH; h++) p[h] = 0.f;

    for (int i = tid; i < INS; i += 128) {
        int idx = x[(size_t)b * INS + i];
        float e = emb[(size_t)idx * SEQL + (SEQL - 1)];
#pragma unroll
        for (int h = 0; h < NH; h++) p[h] = fmaf(e, wir[h * INS + i], p[h]);
    }

    __shared__ float red[4][NH];
#pragma unroll
    for (int h = 0; h < NH; h++) {
        float v = p[h];
#pragma unroll
        for (int o = 16; o; o >>= 1) v += __shfl_xor_sync(0xffffffffu, v, o);
        p[h] = v;
    }
    if ((tid & 31) == 0) {
#pragma unroll
        for (int h = 0; h < NH; h++) red[tid >> 5][h] = p[h];
    }
    __syncthreads();
    if (tid < NH) {
        float s = red[0][tid] + red[1][tid] + red[2][tid] + red[3][tid];
        g_hbwd[b * NH + tid] = tanhf(s + bir[tid] + bhr[tid]);
    }
}

// ---------------------------------------------------------------------------
// Kernel 3: forward scan over 128 steps + fused FC epilogue.
// 16 lanes per batch (h = lane&15, lanes 12..15 ride along), shfl width 16.
// pre layout [s][b][h] -> per-step loads fully coalesced across the block.
// ---------------------------------------------------------------------------
extern "C" __global__ void __launch_bounds__(256)
scan_kernel(const float* __restrict__ whh, const float* __restrict__ bih,
            const float* __restrict__ bhh, const float* __restrict__ fcw,
            const float* __restrict__ fcb, float* __restrict__ out) {
    const int tid = threadIdx.x;
    const int b = blockIdx.x * 16 + (tid >> 4);
    const int hl = tid & 15;
    const int hc = hl < NH ? hl : 0;

    float wrow[NH];
#pragma unroll
    for (int j = 0; j < NH; j++) wrow[j] = whh[hc * NH + j];
    const float bias = bih[hc] + bhh[hc];

    const float* ps = g_pre + (size_t)b * NH + hc;
    float h = 0.f;
    float pnext = ps[0];

    for (int s = 0; s < SEQL; s++) {
        float p = pnext;
        if (s + 1 < SEQL) pnext = ps[(size_t)(s + 1) * NB * NH];
        float v[NH];
#pragma unroll
        for (int j = 0; j < NH; j++) v[j] = __shfl_sync(0xffffffffu, h, j, 16);
        float a0 = fmaf(v[0], wrow[0], p + bias);
        float a1 = v[1] * wrow[1];
        float a2 = v[2] * wrow[2];
#pragma unroll
        for (int j = 3; j < NH; j += 3) {
            a0 = fmaf(v[j    ], wrow[j    ], a0);
            a1 = fmaf(v[j + 1], wrow[j + 1], a1);
            a2 = fmaf(v[j + 2], wrow[j + 2], a2);
        }
        h = tanhf(a0 + a1 + a2);
    }

    // FC epilogue: lanes 0..2 each produce one output
    float v[NH];
#pragma unroll
    for (int j = 0; j < NH; j++) v[j] = __shfl_sync(0xffffffffu, h, j, 16);
    if (hl < NOUT) {
        float o = fcb[hl];
        const float* hb = g_hbwd + (size_t)b * NH;
#pragma unroll
        for (int j = 0; j < NH; j++) o = fmaf(v[j], fcw[hl * 2 * NH + j], o);
#pragma unroll
        for (int j = 0; j < NH; j++) o = fmaf(hb[j], fcw[hl * 2 * NH + NH + j], o);
        out[b * NOUT + hl] = o;
    }
}

// ---------------------------------------------------------------------------
extern "C" void kernel_launch(void* const* d_in, const int* in_sizes, int n_in,
                              void* d_out, int out_size) {
    const int*   x      = (const int*)  d_in[0];
    const float* emb    = (const float*)d_in[1];
    const float* w_ih_f = (const float*)d_in[2];
    const float* w_hh_f = (const float*)d_in[3];
    const float* b_ih_f = (const float*)d_in[4];
    const float* b_hh_f = (const float*)d_in[5];
    const float* w_ih_r = (const float*)d_in[6];
    // d_in[7] = w_hh_r (unused by the reference's consumed output)
    const float* b_ih_r = (const float*)d_in[8];
    const float* b_hh_r = (const float*)d_in[9];
    const float* fc_w   = (const float*)d_in[10];
    const float* fc_b   = (const float*)d_in[11];
    float* out = (float*)d_out;

    const int smem = (int)((size_t)INS * 6 * sizeof(ulonglong2) +
                           (size_t)BPB * INS * sizeof(int));  // 57344 B
    cudaFuncSetAttribute(pre_kernel, cudaFuncAttributeMaxDynamicSharedMemorySize, smem);

    pre_kernel<<<NB / BPB, 128, smem>>>(x, emb, w_ih_f);
    bwd_kernel<<<NB, 128>>>(x, emb, w_ih_r, b_ih_r, b_hh_r);
    scan_kernel<<<NB / 16, 256>>>(w_hh_f, b_ih_f, b_hh_f, fc_w, fc_b, out);
}

// round 2
// speedup vs baseline: 1.2254x; 1.2254x over previous
#include <cuda_runtime.h>
#include <cstdint>

#define NB   2048
#define INS  512
#define SEQL 128
#define NH   12
#define NOUT 3
#define BPB  4   // batches per block in pre_kernel (1 warp per batch)

// scratch (allocation-free contract: __device__ globals)
__device__ float g_pre[(size_t)SEQL * NB * NH];   // [s][b][h]  ~12.6 MB
__device__ float g_hbwd[NB * NH];

__device__ __forceinline__ unsigned long long fma2(unsigned long long a,
                                                   unsigned long long b,
                                                   unsigned long long c) {
    unsigned long long d;
    asm("fma.rn.f32x2 %0, %1, %2, %3;" : "=l"(d) : "l"(a), "l"(b), "l"(c));
    return d;
}
__device__ __forceinline__ unsigned long long pk2(float f) {
    unsigned long long u;
    asm("mov.b64 %0, {%1, %1};" : "=l"(u) : "f"(f));
    return u;
}
__device__ __forceinline__ float ftanh(float x) {
    float e = __expf(2.0f * x);
    return 1.0f - __fdividef(2.0f, e + 1.0f);
}

// ---------------------------------------------------------------------------
// Kernel 1: pre[s,b,h] = sum_i emb[x[b,i], s] * w_ih_f[h,i]
// grid (NB/BPB, 2): y = s-half. Warp per batch; lane owns s = 64*y + 2*lane + {0,1}.
// Weights in smem as float2 pairs (w[2k],w[2k+1]) -> 3 broadcast LDS.128 per i.
// Embedding scalar duplicated in-register (mov.b64 {e,e}) -> 12 fma.rn.f32x2 per i.
// ---------------------------------------------------------------------------
extern "C" __global__ void __launch_bounds__(128)
pre_kernel(const int* __restrict__ x, const float* __restrict__ emb,
           const float* __restrict__ wih) {
    __shared__ float2 w2[INS * 6];   // 24 KB: w2[i*6+k] = (w[2k,i], w[2k+1,i])
    __shared__ int    xs[BPB * INS]; // 8 KB

    const int tid = threadIdx.x;
    const int b0 = blockIdx.x * BPB;

    // stage weight pairs; gmem reads contiguous in i for fixed k
    for (int t = tid; t < INS * 6; t += 128) {
        int i = t & (INS - 1);
        int k = t >> 9;              // 0..5
        float2 p = make_float2(wih[(2 * k) * INS + i], wih[(2 * k + 1) * INS + i]);
        w2[i * 6 + k] = p;
    }
    for (int t = tid; t < BPB * INS; t += 128)
        xs[t] = x[(size_t)b0 * INS + t];
    __syncthreads();

    const int wb = tid >> 5;
    const int lane = tid & 31;
    const int b = b0 + wb;
    const int sbase = blockIdx.y * 64 + lane * 2;
    const int* xrow = xs + wb * INS;

    unsigned long long acc[2][6];
#pragma unroll
    for (int sp = 0; sp < 2; sp++)
#pragma unroll
        for (int k = 0; k < 6; k++) acc[sp][k] = 0ull;

    for (int i0 = 0; i0 < INS; i0 += 4) {
        int4 q = *(const int4*)(xrow + i0);   // broadcast LDS.128, 4 indices
#pragma unroll
        for (int u = 0; u < 4; u++) {
            int idx = (u == 0) ? q.x : (u == 1) ? q.y : (u == 2) ? q.z : q.w;
            float2 e = *(const float2*)(emb + (size_t)idx * SEQL + sbase); // LDG.64 coalesced
            unsigned long long p0 = pk2(e.x);
            unsigned long long p1 = pk2(e.y);
            const ulonglong2* wv = (const ulonglong2*)(w2 + (size_t)(i0 + u) * 6);
            ulonglong2 wA = wv[0], wB = wv[1], wC = wv[2];  // 3 broadcast LDS.128
            acc[0][0] = fma2(p0, wA.x, acc[0][0]);
            acc[1][0] = fma2(p1, wA.x, acc[1][0]);
            acc[0][1] = fma2(p0, wA.y, acc[0][1]);
            acc[1][1] = fma2(p1, wA.y, acc[1][1]);
            acc[0][2] = fma2(p0, wB.x, acc[0][2]);
            acc[1][2] = fma2(p1, wB.x, acc[1][2]);
            acc[0][3] = fma2(p0, wB.y, acc[0][3]);
            acc[1][3] = fma2(p1, wB.y, acc[1][3]);
            acc[0][4] = fma2(p0, wC.x, acc[0][4]);
            acc[1][4] = fma2(p1, wC.x, acc[1][4]);
            acc[0][5] = fma2(p0, wC.y, acc[0][5]);
            acc[1][5] = fma2(p1, wC.y, acc[1][5]);
        }
    }

    // acc[sp][k] = (pre[s, b, 2k], pre[s, b, 2k+1]) -> 12 contiguous floats per s
#pragma unroll
    for (int sp = 0; sp < 2; sp++) {
        int s = sbase + sp;
        ulonglong2* d = (ulonglong2*)(g_pre + ((size_t)s * NB + b) * NH);
        ulonglong2 v0, v1, v2;
        v0.x = acc[sp][0]; v0.y = acc[sp][1];
        v1.x = acc[sp][2]; v1.y = acc[sp][3];
        v2.x = acc[sp][4]; v2.y = acc[sp][5];
        d[0] = v0; d[1] = v1; d[2] = v2;
    }
}

// ---------------------------------------------------------------------------
// Kernel 2: h_bwd[b,h] = tanh( sum_i emb[x[b,i],127]*w_ih_r[h,i] + b_ih_r + b_hh_r )
// Warp per batch, 8 batches/block, w_ih_r staged in smem (conflict-free LDS).
// ---------------------------------------------------------------------------
extern "C" __global__ void __launch_bounds__(256)
bwd_kernel(const int* __restrict__ x, const float* __restrict__ emb,
           const float* __restrict__ wir, const float* __restrict__ bir,
           const float* __restrict__ bhr) {
    __shared__ float ws[NH * INS];   // 24 KB, same [h][i] layout
    const int tid = threadIdx.x;
    for (int t = tid; t < NH * INS; t += 256) ws[t] = wir[t];
    __syncthreads();

    const int warp = tid >> 5, lane = tid & 31;
    const int b = blockIdx.x * 8 + warp;

    float p[NH];
#pragma unroll
    for (int h = 0; h < NH; h++) p[h] = 0.f;

    for (int i = lane; i < INS; i += 32) {
        int idx = x[(size_t)b * INS + i];
        float e = emb[(size_t)idx * SEQL + (SEQL - 1)];
#pragma unroll
        for (int h = 0; h < NH; h++) p[h] = fmaf(e, ws[h * INS + i], p[h]);
    }
#pragma unroll
    for (int h = 0; h < NH; h++) {
        float v = p[h];
#pragma unroll
        for (int o = 16; o; o >>= 1) v += __shfl_xor_sync(0xffffffffu, v, o);
        p[h] = v;
    }
    if (lane < NH)
        g_hbwd[b * NH + lane] =
            ftanh(__shfl_sync(0xffffffffu, p[0], 0) * 0.f +  // keep lane0 sums? no:
                  0.f);
}

// NOTE: the shfl-reduced sums live in lane 0's p[]; rewrite tail properly below.
// (bwd_kernel above replaced by bwd_kernel2 actually used)
extern "C" __global__ void __launch_bounds__(256)
bwd_kernel2(const int* __restrict__ x, const float* __restrict__ emb,
            const float* __restrict__ wir, const float* __restrict__ bir,
            const float* __restrict__ bhr) {
    __shared__ float ws[NH * INS];   // 24 KB
    const int tid = threadIdx.x;
    for (int t = tid; t < NH * INS; t += 256) ws[t] = wir[t];
    __syncthreads();

    const int warp = tid >> 5, lane = tid & 31;
    const int b = blockIdx.x * 8 + warp;

    float p[NH];
#pragma unroll
    for (int h = 0; h < NH; h++) p[h] = 0.f;

    for (int i = lane; i < INS; i += 32) {
        int idx = x[(size_t)b * INS + i];
        float e = emb[(size_t)idx * SEQL + (SEQL - 1)];
#pragma unroll
        for (int h = 0; h < NH; h++) p[h] = fmaf(e, ws[h * INS + i], p[h]);
    }
    // butterfly reduce: every lane ends with the full sum for each h
#pragma unroll
    for (int h = 0; h < NH; h++) {
        float v = p[h];
#pragma unroll
        for (int o = 16; o; o >>= 1) v += __shfl_xor_sync(0xffffffffu, v, o);
        p[h] = v;
    }
    if (lane == 0) {
        float r[NH];
#pragma unroll
        for (int h = 0; h < NH; h++) r[h] = ftanh(p[h] + bir[h] + bhr[h]);
        float4* d = (float4*)(g_hbwd + (size_t)b * NH);
        d[0] = make_float4(r[0], r[1], r[2], r[3]);
        d[1] = make_float4(r[4], r[5], r[6], r[7]);
        d[2] = make_float4(r[8], r[9], r[10], r[11]);
    }
}

// ---------------------------------------------------------------------------
// Kernel 3: forward scan over 128 steps + fused FC epilogue.
// 16 lanes per batch (h = lane&15), shfl width 16. Fast tanh via __expf.
// ---------------------------------------------------------------------------
extern "C" __global__ void __launch_bounds__(256)
scan_kernel(const float* __restrict__ whh, const float* __restrict__ bih,
            const float* __restrict__ bhh, const float* __restrict__ fcw,
            const float* __restrict__ fcb, float* __restrict__ out) {
    const int tid = threadIdx.x;
    const int b = blockIdx.x * 16 + (tid >> 4);
    const int hl = tid & 15;
    const int hc = hl < NH ? hl : 0;

    float wrow[NH];
#pragma unroll
    for (int j = 0; j < NH; j++) wrow[j] = whh[hc * NH + j];
    const float bias = bih[hc] + bhh[hc];

    const float* ps = g_pre + (size_t)b * NH + hc;
    float h = 0.f;
    float pnext = ps[0];

    for (int s = 0; s < SEQL; s++) {
        float p = pnext;
        if (s + 1 < SEQL) pnext = ps[(size_t)(s + 1) * NB * NH];
        float v[NH];
#pragma unroll
        for (int j = 0; j < NH; j++) v[j] = __shfl_sync(0xffffffffu, h, j, 16);
        float a0 = fmaf(v[0], wrow[0], p + bias);
        float a1 = v[1] * wrow[1];
        float a2 = v[2] * wrow[2];
#pragma unroll
        for (int j = 3; j < NH; j += 3) {
            a0 = fmaf(v[j    ], wrow[j    ], a0);
            a1 = fmaf(v[j + 1], wrow[j + 1], a1);
            a2 = fmaf(v[j + 2], wrow[j + 2], a2);
        }
        h = ftanh(a0 + a1 + a2);
    }

    float v[NH];
#pragma unroll
    for (int j = 0; j < NH; j++) v[j] = __shfl_sync(0xffffffffu, h, j, 16);
    if (hl < NOUT) {
        float o = fcb[hl];
        const float* hb = g_hbwd + (size_t)b * NH;
#pragma unroll
        for (int j = 0; j < NH; j++) o = fmaf(v[j], fcw[hl * 2 * NH + j], o);
#pragma unroll
        for (int j = 0; j < NH; j++) o = fmaf(hb[j], fcw[hl * 2 * NH + NH + j], o);
        out[b * NOUT + hl] = o;
    }
}

// ---------------------------------------------------------------------------
extern "C" void kernel_launch(void* const* d_in, const int* in_sizes, int n_in,
                              void* d_out, int out_size) {
    const int*   x      = (const int*)  d_in[0];
    const float* emb    = (const float*)d_in[1];
    const float* w_ih_f = (const float*)d_in[2];
    const float* w_hh_f = (const float*)d_in[3];
    const float* b_ih_f = (const float*)d_in[4];
    const float* b_hh_f = (const float*)d_in[5];
    const float* w_ih_r = (const float*)d_in[6];
    // d_in[7] = w_hh_r (unused: reference consumes only the one-step reverse state)
    const float* b_ih_r = (const float*)d_in[8];
    const float* b_hh_r = (const float*)d_in[9];
    const float* fc_w   = (const float*)d_in[10];
    const float* fc_b   = (const float*)d_in[11];
    float* out = (float*)d_out;

    bwd_kernel2<<<NB / 8, 256>>>(x, emb, w_ih_r, b_ih_r, b_hh_r);
    pre_kernel<<<dim3(NB / BPB, 2), 128>>>(x, emb, w_ih_f);
    scan_kernel<<<NB / 16, 256>>>(w_hh_f, b_ih_f, b_hh_f, fc_w, fc_b, out);
}